// round 4
// baseline (speedup 1.0000x reference)
#include <cuda_runtime.h>
#include <cuda_fp16.h>
#include <cstdint>

#define BB   256
#define TT   256
#define KTOK 128
#define HH   512
#define G4H  2048
#define DD   128

#define NCTA 64
#define NTHR 256

#define A_PITCH  272u                   // 128 k halves * 2B + 16B pad
#define A_BUF    (128u * A_PITCH)       // 34816 per buffer
#define BG_PITCH 144u                   // 64 gate cols * 2B + 16B pad
#define BO_PITCH 16u                    // 8 cols (4 real + 4 pad) * 2B

#define A_OFF   0u
#define BG_OFF  (2u * A_BUF)                    // 69632
#define BO_OFF  (BG_OFF + 512u * BG_PITCH)      // 143360
#define XG_OFF  (BO_OFF + 512u * BO_PITCH)      // 151552
#define SMEM_BYTES (XG_OFF + 256u)              // 151808

__device__ __half    g_h[2][BB * HH];
__device__ unsigned  g_cnt[8 * 32];     // 8 group counters, 128B apart
__device__ unsigned  g_rel;

__global__ void reset_kernel() {
    if (threadIdx.x < 8 * 32) g_cnt[threadIdx.x] = 0u;
    if (threadIdx.x == 0) g_rel = 0u;
}

__device__ __forceinline__ uint32_t smem_u32(const void* p) {
    uint32_t a;
    asm("{ .reg .u64 t; cvta.to.shared.u64 t, %1; cvt.u32.u64 %0, t; }" : "=r"(a) : "l"(p));
    return a;
}
__device__ __forceinline__ float tanha(float x) {
    float r; asm("tanh.approx.f32 %0, %1;" : "=f"(r) : "f"(x)); return r;
}
__device__ __forceinline__ float sigm(float x) { return fmaf(0.5f, tanha(0.5f * x), 0.5f); }

__device__ __forceinline__ void ldsm_x4(uint32_t* r, uint32_t addr) {
    asm volatile("ldmatrix.sync.aligned.m8n8.x4.shared.b16 {%0,%1,%2,%3}, [%4];"
        : "=r"(r[0]), "=r"(r[1]), "=r"(r[2]), "=r"(r[3]) : "r"(addr));
}
__device__ __forceinline__ void ldsm_x4t(uint32_t* r, uint32_t addr) {
    asm volatile("ldmatrix.sync.aligned.m8n8.x4.trans.shared.b16 {%0,%1,%2,%3}, [%4];"
        : "=r"(r[0]), "=r"(r[1]), "=r"(r[2]), "=r"(r[3]) : "r"(addr));
}
__device__ __forceinline__ void ldsm_x2t(uint32_t* r, uint32_t addr) {
    asm volatile("ldmatrix.sync.aligned.m8n8.x2.trans.shared.b16 {%0,%1}, [%2];"
        : "=r"(r[0]), "=r"(r[1]) : "r"(addr));
}
__device__ __forceinline__ void mma16816(float* d, const uint32_t* a, const uint32_t* b) {
    asm volatile("mma.sync.aligned.m16n8k16.row.col.f32.f16.f16.f32 "
        "{%0,%1,%2,%3}, {%4,%5,%6,%7}, {%8,%9}, {%0,%1,%2,%3};"
        : "+f"(d[0]), "+f"(d[1]), "+f"(d[2]), "+f"(d[3])
        : "r"(a[0]), "r"(a[1]), "r"(a[2]), "r"(a[3]), "r"(b[0]), "r"(b[1]));
}

// ---- tree grid barrier: 64 CTAs = 8 groups x 8 -------------------------------
__device__ __forceinline__ void gridbar(unsigned ep) {
    __syncthreads();
    if (threadIdx.x == 0) {
        __threadfence();
        atomicAdd(&g_cnt[(blockIdx.x & 7) * 32], 1u);
    }
    if (blockIdx.x == 0) {
        if (threadIdx.x < 8) {
            const unsigned target = ep * 8u;
            while (*(volatile unsigned*)&g_cnt[threadIdx.x * 32] < target) {}
        }
        __syncthreads();
        if (threadIdx.x == 0) { __threadfence(); atomicExch(&g_rel, ep); }
    }
    if (threadIdx.x == 0) {
        while (*(volatile unsigned*)&g_rel < ep) {}
        __threadfence();
    }
    __syncthreads();
}

__global__ void __launch_bounds__(NTHR, 1) lstm_mma_kernel(
    const float* __restrict__ z,     const float* __restrict__ Wz,
    const float* __restrict__ bz,    const float* __restrict__ token,
    const float* __restrict__ Wi,    const float* __restrict__ Wh,
    const float* __restrict__ bh,    const float* __restrict__ Wout,
    const float* __restrict__ bout,  float* __restrict__ out)
{
    extern __shared__ char smem[];
    const uint32_t sb = smem_u32(smem);

    const int tid  = threadIdx.x;
    const int lane = tid & 31;
    const int w    = tid >> 5;            // warp 0..7 (m-tile)
    const int mh   = blockIdx.x & 1;      // batch half
    const int jg   = blockIdx.x >> 1;     // unit group 0..31 (16 units)
    const int m0   = mh * 128;
    const int j0   = jg * 16;

    // mma fragment geometry
    const int qr   = lane >> 2;           // 0..7
    const int qc   = lane & 3;            // 0..3
    const int row0 = w * 16 + qr;

    // ldmatrix lane base addresses
    const int grp = lane >> 3, li = lane & 7;
    const uint32_t aLane  = sb + A_OFF + (uint32_t)(w * 16 + (grp & 1) * 8 + li) * A_PITCH
                          + (uint32_t)(grp >> 1) * 16u;
    const uint32_t bgLane = sb + BG_OFF + (uint32_t)(lane & 15) * BG_PITCH
                          + (uint32_t)(lane >> 4) * 16u;
    const uint32_t boLane = sb + BO_OFF + (uint32_t)(lane & 15) * BO_PITCH;

    // A staging map
    const int lm = tid >> 4;              // row 0..15 (+16s)
    const int lc = tid & 15;              // 16B granule

    float* sxg = (float*)(smem + XG_OFF);

    // ---------------- one-time init ----------------
    // Wh slice -> fp16 smem [k][n], n = gate*16 + unit
    for (int idx = tid; idx < 512 * 64; idx += NTHR) {
        int k = idx >> 6, n = idx & 63;
        float v = __ldg(&Wh[(size_t)k * G4H + (n >> 4) * HH + j0 + (n & 15)]);
        *(__half*)(smem + BG_OFF + (uint32_t)k * BG_PITCH + (uint32_t)n * 2u) = __float2half_rn(v);
    }
    // x_gates = token @ Wi + bh
    if (tid < 64) {
        int col = (tid >> 4) * HH + j0 + (tid & 15);
        float s = bh[col];
        #pragma unroll 4
        for (int k = 0; k < KTOK; ++k)
            s = fmaf(token[k], __ldg(&Wi[(size_t)k * G4H + col]), s);
        sxg[tid] = s;
    }
    // h0 = relu(z @ Wz + bz): thread -> row tid>>1, 8 units
    {
        const int r  = tid >> 1;
        const int ub = (tid & 1) * 8;
        float a[8];
        #pragma unroll
        for (int q = 0; q < 8; ++q) a[q] = bz[j0 + ub + q];
        const float* zr = z + (size_t)(m0 + r) * KTOK;
        #pragma unroll 4
        for (int k = 0; k < KTOK; ++k) {
            float zv = __ldg(zr + k);
            const float4* wr = (const float4*)&Wz[(size_t)k * HH + j0 + ub];
            float4 w0 = __ldg(wr), w1 = __ldg(wr + 1);
            a[0] = fmaf(zv, w0.x, a[0]); a[1] = fmaf(zv, w0.y, a[1]);
            a[2] = fmaf(zv, w0.z, a[2]); a[3] = fmaf(zv, w0.w, a[3]);
            a[4] = fmaf(zv, w1.x, a[4]); a[5] = fmaf(zv, w1.y, a[5]);
            a[6] = fmaf(zv, w1.z, a[6]); a[7] = fmaf(zv, w1.w, a[7]);
        }
        __half2* hp = (__half2*)&g_h[0][(size_t)(m0 + r) * HH + j0 + ub];
        #pragma unroll
        for (int q = 0; q < 4; ++q)
            hp[q] = __floats2half2_rn(fmaxf(a[2 * q], 0.f), fmaxf(a[2 * q + 1], 0.f));
    }
    unsigned ep = 1;
    gridbar(ep++);

    float c8[8];
    #pragma unroll
    for (int e = 0; e < 8; ++e) c8[e] = 0.f;
    float4 wo[2];

    // ---------------- sequential loop ----------------
    #pragma unroll 1
    for (int t = 0; t <= TT; ++t) {
        const __half* hsrc = g_h[t & 1];
        const int te = t - 1;

        // STS Wout_{t-1} (prefetched last iter) into BO
        if (t >= 1) {
            #pragma unroll
            for (int r = 0; r < 2; ++r) {
                int k = tid * 2 + r;
                __half2 p01 = __floats2half2_rn(wo[r].x, wo[r].y);
                __half2 p23 = __floats2half2_rn(wo[r].z, wo[r].w);
                uint2 pk;
                pk.x = *(uint32_t*)&p01; pk.y = *(uint32_t*)&p23;
                *(uint2*)(smem + BO_OFF + (uint32_t)k * BO_PITCH) = pk;
            }
        }

        float acc[9][4];
        #pragma unroll
        for (int n = 0; n < 9; ++n)
            #pragma unroll
            for (int e = 0; e < 4; ++e) acc[n][e] = 0.f;

        // prologue: chunk0 loads
        uint4 v[8];
        #pragma unroll
        for (int s = 0; s < 8; ++s)
            v[s] = __ldcg((const uint4*)&hsrc[(size_t)(m0 + lm + 16 * s) * HH + lc * 8]);

        // prefetch Wout_t for next iteration (off critical path)
        if (t < TT) {
            const float* Wo = Wout + (size_t)t * HH * DD + jg * 4;
            wo[0] = __ldcg((const float4*)(Wo + (size_t)(tid * 2) * DD));
            wo[1] = __ldcg((const float4*)(Wo + (size_t)(tid * 2 + 1) * DD));
        }

        #pragma unroll
        for (int s = 0; s < 8; ++s)
            *(uint4*)(smem + A_OFF + (uint32_t)(lm + 16 * s) * A_PITCH + (uint32_t)lc * 16u) = v[s];
        #pragma unroll
        for (int s = 0; s < 8; ++s)
            v[s] = __ldcg((const uint4*)&hsrc[(size_t)(m0 + lm + 16 * s) * HH + 128 + lc * 8]);
        __syncthreads();

        #pragma unroll
        for (int kc = 0; kc < 4; ++kc) {
            const uint32_t buf = (uint32_t)(kc & 1);
            if (kc < 3) {
                const uint32_t nb = buf ^ 1u;
                #pragma unroll
                for (int s = 0; s < 8; ++s)
                    *(uint4*)(smem + A_OFF + nb * A_BUF + (uint32_t)(lm + 16 * s) * A_PITCH + (uint32_t)lc * 16u) = v[s];
            }
            if (kc < 2) {
                #pragma unroll
                for (int s = 0; s < 8; ++s)
                    v[s] = __ldcg((const uint4*)&hsrc[(size_t)(m0 + lm + 16 * s) * HH + (kc + 2) * 128 + lc * 8]);
            }
            const uint32_t aA = aLane + buf * A_BUF;
            #pragma unroll
            for (int kf = 0; kf < 8; ++kf) {
                const uint32_t krow = (uint32_t)(kc * 128 + kf * 16);
                uint32_t a[4], bb[4], b2[2];
                ldsm_x4(a, aA + (uint32_t)kf * 32u);
                #pragma unroll
                for (int p = 0; p < 4; ++p) {
                    ldsm_x4t(bb, bgLane + krow * BG_PITCH + (uint32_t)p * 32u);
                    mma16816(acc[2 * p], a, bb);
                    mma16816(acc[2 * p + 1], a, bb + 2);
                }
                ldsm_x2t(b2, boLane + krow * BO_PITCH);
                mma16816(acc[8], a, b2);
            }
            if (kc < 3) __syncthreads();
        }

        // ---- out store (4 cols per CTA; qc<2 holds real cols) ----
        if (t >= 1 && qc < 2) {
            const float2 bo = *(const float2*)&bout[te * DD + jg * 4 + qc * 2];
            float2 o0 = make_float2(acc[8][0] + bo.x, acc[8][1] + bo.y);
            float2 o1 = make_float2(acc[8][2] + bo.x, acc[8][3] + bo.y);
            *(float2*)&out[(size_t)(m0 + row0) * TT * DD + (size_t)te * DD + jg * 4 + qc * 2] = o0;
            *(float2*)&out[(size_t)(m0 + row0 + 8) * TT * DD + (size_t)te * DD + jg * 4 + qc * 2] = o1;
        }

        // ---- cell update (registers) + h store ----
        if (t < TT) {
            __half* hdst = &g_h[(t + 1) & 1][0];
            #pragma unroll
            for (int hh = 0; hh < 2; ++hh) {
                #pragma unroll
                for (int r = 0; r < 2; ++r) {
                    float hv[2];
                    #pragma unroll
                    for (int cc = 0; cc < 2; ++cc) {
                        const int u = hh * 8 + qc * 2 + cc;
                        const int e = r * 2 + cc;
                        const int ci = hh * 4 + r * 2 + cc;
                        float gi = sigm (acc[0 + hh][e] + sxg[u]);
                        float gf = sigm (acc[2 + hh][e] + sxg[16 + u]);
                        float gg = tanha(acc[4 + hh][e] + sxg[32 + u]);
                        float go = sigm (acc[6 + hh][e] + sxg[48 + u]);
                        float cv = gf * c8[ci] + gi * gg;
                        c8[ci] = cv;
                        hv[cc] = go * tanha(cv);
                    }
                    *(__half2*)&hdst[(size_t)(m0 + row0 + r * 8) * HH + j0 + hh * 8 + qc * 2] =
                        __floats2half2_rn(hv[0], hv[1]);
                }
            }
            gridbar(ep++);
        }
    }
}

extern "C" void kernel_launch(void* const* d_in, const int* in_sizes, int n_in,
                              void* d_out, int out_size) {
    const float* z     = (const float*)d_in[0];
    const float* Wz    = (const float*)d_in[1];
    const float* bz    = (const float*)d_in[2];
    const float* token = (const float*)d_in[3];
    const float* Wi    = (const float*)d_in[4];
    const float* Wh    = (const float*)d_in[5];
    const float* bh    = (const float*)d_in[6];
    const float* Wout  = (const float*)d_in[7];
    const float* bout  = (const float*)d_in[8];
    float* out = (float*)d_out;

    cudaFuncSetAttribute(lstm_mma_kernel, cudaFuncAttributeMaxDynamicSharedMemorySize, SMEM_BYTES);
    reset_kernel<<<1, 256>>>();
    lstm_mma_kernel<<<NCTA, NTHR, SMEM_BYTES>>>(z, Wz, bz, token, Wi, Wh, bh, Wout, bout, out);
}

// round 5
// speedup vs baseline: 1.2533x; 1.2533x over previous
#include <cuda_runtime.h>
#include <cuda_fp16.h>
#include <cstdint>

#define BB   256
#define TT   256
#define KTOK 128
#define HH   512
#define G4H  2048
#define DD   128

#define NCTA 128
#define NTHR 256

#define A_PITCH  272u                   // 128 k halves * 2B + 16B pad
#define A_BUF    (128u * A_PITCH)       // 34816 per chunk buffer
#define BG_PITCH 80u                    // 32 gate cols * 2B + 16B pad
#define BO_PITCH 16u                    // 8 cols (2 real + 6 pad) * 2B

#define A_OFF   0u
#define BG_OFF  (4u * A_BUF)                    // 139264
#define BO_OFF  (BG_OFF + 512u * BG_PITCH)      // 180224
#define XG_OFF  (BO_OFF + 512u * BO_PITCH)      // 188416
#define SMEM_BYTES (XG_OFF + 128u)              // 188544

__device__ __half    g_h[2][BB * HH];
__device__ unsigned  g_cnt[2 * 32];     // per-half arrival counters (128B apart)
__device__ unsigned  g_rel[2 * 32];     // per-half release flags

__global__ void reset_kernel() {
    if (threadIdx.x < 64) { g_cnt[threadIdx.x] = 0u; g_rel[threadIdx.x] = 0u; }
}

__device__ __forceinline__ uint32_t smem_u32(const void* p) {
    uint32_t a;
    asm("{ .reg .u64 t; cvta.to.shared.u64 t, %1; cvt.u32.u64 %0, t; }" : "=r"(a) : "l"(p));
    return a;
}
__device__ __forceinline__ float tanha(float x) {
    float r; asm("tanh.approx.f32 %0, %1;" : "=f"(r) : "f"(x)); return r;
}
__device__ __forceinline__ float sigm(float x) { return fmaf(0.5f, tanha(0.5f * x), 0.5f); }

__device__ __forceinline__ void ldsm_x4(uint32_t* r, uint32_t addr) {
    asm volatile("ldmatrix.sync.aligned.m8n8.x4.shared.b16 {%0,%1,%2,%3}, [%4];"
        : "=r"(r[0]), "=r"(r[1]), "=r"(r[2]), "=r"(r[3]) : "r"(addr));
}
__device__ __forceinline__ void ldsm_x4t(uint32_t* r, uint32_t addr) {
    asm volatile("ldmatrix.sync.aligned.m8n8.x4.trans.shared.b16 {%0,%1,%2,%3}, [%4];"
        : "=r"(r[0]), "=r"(r[1]), "=r"(r[2]), "=r"(r[3]) : "r"(addr));
}
__device__ __forceinline__ void ldsm_x2t(uint32_t* r, uint32_t addr) {
    asm volatile("ldmatrix.sync.aligned.m8n8.x2.trans.shared.b16 {%0,%1}, [%2];"
        : "=r"(r[0]), "=r"(r[1]) : "r"(addr));
}
__device__ __forceinline__ void mma16816(float* d, const uint32_t* a, const uint32_t* b) {
    asm volatile("mma.sync.aligned.m16n8k16.row.col.f32.f16.f16.f32 "
        "{%0,%1,%2,%3}, {%4,%5,%6,%7}, {%8,%9}, {%0,%1,%2,%3};"
        : "+f"(d[0]), "+f"(d[1]), "+f"(d[2]), "+f"(d[3])
        : "r"(a[0]), "r"(a[1]), "r"(a[2]), "r"(a[3]), "r"(b[0]), "r"(b[1]));
}

#define CP_ASYNC16(dst, src) asm volatile("cp.async.cg.shared.global [%0], [%1], 16;" :: "r"(dst), "l"(src) : "memory")
#define CP_COMMIT()          asm volatile("cp.async.commit_group;" ::: "memory")
#define CP_WAIT(n)           asm volatile("cp.async.wait_group %0;" :: "n"(n) : "memory")

__global__ void __launch_bounds__(NTHR, 1) lstm_mma_kernel(
    const float* __restrict__ z,     const float* __restrict__ Wz,
    const float* __restrict__ bz,    const float* __restrict__ token,
    const float* __restrict__ Wi,    const float* __restrict__ Wh,
    const float* __restrict__ bh,    const float* __restrict__ Wout,
    const float* __restrict__ bout,  float* __restrict__ out)
{
    extern __shared__ char smem[];
    const uint32_t sb = smem_u32(smem);

    const int tid  = threadIdx.x;
    const int lane = tid & 31;
    const int w    = tid >> 5;            // warp 0..7 (m-tile)
    const int mh   = blockIdx.x & 1;      // batch half (independent sync domain)
    const int jg   = blockIdx.x >> 1;     // unit group 0..63 (8 units)
    const int m0   = mh * 128;
    const int j0   = jg * 8;
    const bool isMaster = (blockIdx.x >> 1) == 0;

    const int qr   = lane >> 2;
    const int qc   = lane & 3;
    const int row0 = w * 16 + qr;
    const int u0   = qc * 2;

    const int grp = lane >> 3, li = lane & 7;
    const uint32_t aLane  = sb + A_OFF + (uint32_t)(w * 16 + (grp & 1) * 8 + li) * A_PITCH
                          + (uint32_t)(grp >> 1) * 16u;
    const uint32_t bgLane = sb + BG_OFF + (uint32_t)(lane & 15) * BG_PITCH
                          + (uint32_t)(lane >> 4) * 16u;
    const uint32_t boLane = sb + BO_OFF + (uint32_t)(lane & 15) * BO_PITCH;

    const int lm = tid >> 4;              // A staging: row (+16s)
    const int lc = tid & 15;              // 16B granule

    float* sxg = (float*)(smem + XG_OFF);
    volatile unsigned* myCnt = &g_cnt[mh * 32];
    volatile unsigned* myRel = &g_rel[mh * 32];

    // ---------------- one-time init ----------------
    for (int i = tid; i < 512; i += NTHR) ((uint4*)(smem + BO_OFF))[i] = make_uint4(0, 0, 0, 0);

    for (int idx = tid; idx < 512 * 32; idx += NTHR) {
        int k = idx >> 5, n = idx & 31;
        float v = __ldg(&Wh[(size_t)k * G4H + (n >> 3) * HH + j0 + (n & 7)]);
        *(__half*)(smem + BG_OFF + (uint32_t)k * BG_PITCH + (uint32_t)n * 2u) = __float2half_rn(v);
    }
    if (tid < 32) {
        int col = (tid >> 3) * HH + j0 + (tid & 7);
        float s = bh[col];
        #pragma unroll 4
        for (int k = 0; k < KTOK; ++k)
            s = fmaf(token[k], __ldg(&Wi[(size_t)k * G4H + col]), s);
        sxg[tid] = s;
    }
    {   // h0 = relu(z @ Wz + bz): thread -> row tid>>1, 4 units
        const int r  = tid >> 1;
        const int ub = (tid & 1) * 4;
        float a[4];
        #pragma unroll
        for (int q = 0; q < 4; ++q) a[q] = bz[j0 + ub + q];
        const float* zr = z + (size_t)(m0 + r) * KTOK;
        #pragma unroll 4
        for (int k = 0; k < KTOK; ++k) {
            float zv = __ldg(zr + k);
            float4 w4 = __ldg((const float4*)&Wz[(size_t)k * HH + j0 + ub]);
            a[0] = fmaf(zv, w4.x, a[0]); a[1] = fmaf(zv, w4.y, a[1]);
            a[2] = fmaf(zv, w4.z, a[2]); a[3] = fmaf(zv, w4.w, a[3]);
        }
        __half2* hp = (__half2*)&g_h[0][(size_t)(m0 + r) * HH + j0 + ub];
        hp[0] = __floats2half2_rn(fmaxf(a[0], 0.f), fmaxf(a[1], 0.f));
        hp[1] = __floats2half2_rn(fmaxf(a[2], 0.f), fmaxf(a[3], 0.f));
    }

    // initial per-half barrier (ep = 1)
    unsigned ep = 1;
    {
        __syncthreads();
        if (tid == 0) {
            __threadfence();
            asm volatile("red.global.add.u32 [%0], %1;" :: "l"((unsigned*)myCnt), "r"(1u) : "memory");
        }
        if (isMaster && tid == 0) {
            while (*myCnt < ep * 64u) {}
            __threadfence();
            atomicExch((unsigned*)myRel, ep);
        }
        if (tid == 0) { while (*myRel < ep) {} __threadfence(); }
        __syncthreads();
    }
    ++ep;

    float c4[4] = {0.f, 0.f, 0.f, 0.f};
    float2 wo0, wo1;

    // ---------------- sequential loop ----------------
    #pragma unroll 1
    for (int t = 0; t <= TT; ++t) {
        const __half* hsrc = g_h[t & 1];
        const int te = t - 1;

        // issue all 4 A chunks via cp.async (one commit group each)
        #define CHUNK_ISSUE(KC)                                                                   \
        {                                                                                         \
            const char* src = (const char*)&hsrc[(size_t)(m0 + lm) * HH + (KC) * 128 + lc * 8];   \
            uint32_t dst = sb + A_OFF + (KC) * A_BUF + (uint32_t)lm * A_PITCH + (uint32_t)lc * 16u; \
            _Pragma("unroll")                                                                     \
            for (int s = 0; s < 8; ++s)                                                           \
                CP_ASYNC16(dst + (uint32_t)s * (16u * A_PITCH), src + (size_t)s * 16 * HH * 2);   \
            CP_COMMIT();                                                                          \
        }
        CHUNK_ISSUE(0) CHUNK_ISSUE(1) CHUNK_ISSUE(2) CHUNK_ISSUE(3)
        #undef CHUNK_ISSUE

        // prefetch Wout_t for next iteration (in flight during mainloop)
        if (t < TT) {
            const float* Wo = Wout + (size_t)t * HH * DD + jg * 2;
            wo0 = __ldcg((const float2*)(Wo + (size_t)(tid * 2) * DD));
            wo1 = __ldcg((const float2*)(Wo + (size_t)(tid * 2 + 1) * DD));
        }

        float acc[5][4];
        #pragma unroll
        for (int n = 0; n < 5; ++n)
            #pragma unroll
            for (int e = 0; e < 4; ++e) acc[n][e] = 0.f;

        #define CHUNK_COMPUTE(KC, WAITN)                                                  \
        {                                                                                 \
            CP_WAIT(WAITN);                                                               \
            __syncthreads();                                                              \
            const uint32_t aA = aLane + (KC) * A_BUF;                                     \
            _Pragma("unroll")                                                             \
            for (int kf = 0; kf < 8; ++kf) {                                              \
                const uint32_t krow = (uint32_t)((KC) * 128 + kf * 16);                   \
                uint32_t a[4], b1[4], b2[4], b3[2];                                       \
                ldsm_x4(a, aA + (uint32_t)kf * 32u);                                      \
                ldsm_x4t(b1, bgLane + krow * BG_PITCH);                                   \
                ldsm_x4t(b2, bgLane + krow * BG_PITCH + 32u);                             \
                ldsm_x2t(b3, boLane + krow * BO_PITCH);                                   \
                mma16816(acc[0], a, b1); mma16816(acc[1], a, b1 + 2);                     \
                mma16816(acc[2], a, b2); mma16816(acc[3], a, b2 + 2);                     \
                mma16816(acc[4], a, b3);                                                  \
            }                                                                             \
        }
        CHUNK_COMPUTE(0, 3) CHUNK_COMPUTE(1, 2) CHUNK_COMPUTE(2, 1) CHUNK_COMPUTE(3, 0)
        #undef CHUNK_COMPUTE

        // ---- critical path: cell update + h store ----
        if (t < TT) {
            __half* hdst = &g_h[(t + 1) & 1][0];
            float hv[4];
            #pragma unroll
            for (int e = 0; e < 4; ++e) {
                const int u = u0 + (e & 1);
                float gi = sigm (acc[0][e] + sxg[u]);
                float gf = sigm (acc[1][e] + sxg[8 + u]);
                float gg = tanha(acc[2][e] + sxg[16 + u]);
                float go = sigm (acc[3][e] + sxg[24 + u]);
                float cv = gf * c4[e] + gi * gg;
                c4[e] = cv;
                hv[e] = go * tanha(cv);
            }
            *(__half2*)&hdst[(size_t)(m0 + row0) * HH + j0 + u0]     = __floats2half2_rn(hv[0], hv[1]);
            *(__half2*)&hdst[(size_t)(m0 + row0 + 8) * HH + j0 + u0] = __floats2half2_rn(hv[2], hv[3]);
        }

        // ---- barrier arrive (also serves as sync before BO overwrite) ----
        __syncthreads();
        if (t < TT && tid == 0) {
            __threadfence();
            asm volatile("red.global.add.u32 [%0], %1;" :: "l"((unsigned*)myCnt), "r"(1u) : "memory");
        }

        // ---- shadow work: out store + next-step Wout STS ----
        if (t >= 1 && qc == 0) {
            const float2 bo = *(const float2*)&bout[te * DD + jg * 2];
            float2 o0 = make_float2(acc[4][0] + bo.x, acc[4][1] + bo.y);
            float2 o1 = make_float2(acc[4][2] + bo.x, acc[4][3] + bo.y);
            *(float2*)&out[(size_t)(m0 + row0) * TT * DD + (size_t)te * DD + jg * 2] = o0;
            *(float2*)&out[(size_t)(m0 + row0 + 8) * TT * DD + (size_t)te * DD + jg * 2] = o1;
        }
        if (t < TT) {
            __half2 p0 = __floats2half2_rn(wo0.x, wo0.y);
            __half2 p1 = __floats2half2_rn(wo1.x, wo1.y);
            *(uint32_t*)(smem + BO_OFF + (uint32_t)(tid * 2) * BO_PITCH)     = *(uint32_t*)&p0;
            *(uint32_t*)(smem + BO_OFF + (uint32_t)(tid * 2 + 1) * BO_PITCH) = *(uint32_t*)&p1;
        }

        // ---- barrier wait ----
        if (t < TT) {
            if (isMaster && tid == 0) {
                while (*myCnt < ep * 64u) {}
                __threadfence();
                atomicExch((unsigned*)myRel, ep);
            }
            if (tid == 0) { while (*myRel < ep) {} __threadfence(); }
            __syncthreads();
            ++ep;
        }
    }
}

extern "C" void kernel_launch(void* const* d_in, const int* in_sizes, int n_in,
                              void* d_out, int out_size) {
    const float* z     = (const float*)d_in[0];
    const float* Wz    = (const float*)d_in[1];
    const float* bz    = (const float*)d_in[2];
    const float* token = (const float*)d_in[3];
    const float* Wi    = (const float*)d_in[4];
    const float* Wh    = (const float*)d_in[5];
    const float* bh    = (const float*)d_in[6];
    const float* Wout  = (const float*)d_in[7];
    const float* bout  = (const float*)d_in[8];
    float* out = (float*)d_out;

    cudaFuncSetAttribute(lstm_mma_kernel, cudaFuncAttributeMaxDynamicSharedMemorySize, SMEM_BYTES);
    reset_kernel<<<1, 64>>>();
    lstm_mma_kernel<<<NCTA, NTHR, SMEM_BYTES>>>(z, Wz, bz, token, Wi, Wh, bh, Wout, bout, out);
}

// round 6
// speedup vs baseline: 1.7618x; 1.4057x over previous
#include <cuda_runtime.h>
#include <cuda_fp16.h>
#include <cstdint>

#define BB   256
#define TT   256
#define KTOK 128
#define HH   512
#define G4H  2048
#define DD   128

#define NCTA 128
#define NTHR 256

#define BG_PITCH 80u                    // 32 gate cols * 2B + 16B pad
#define BO_PITCH 16u                    // 8 cols (2 real + 6 pad) * 2B
#define BO_BUF   8192u

#define BG_OFF  0u
#define BO_OFF  40960u                  // 2 buffers x 8192
#define XG_OFF  57344u
#define SMEM_BYTES 57472u

__device__ __half    g_h[2][BB * HH];
__device__ unsigned  g_cnt[2 * 32];     // per-half arrival counters (128B apart)

__global__ void reset_kernel() { if (threadIdx.x < 64) g_cnt[threadIdx.x] = 0u; }

__device__ __forceinline__ uint32_t smem_u32(const void* p) {
    uint32_t a;
    asm("{ .reg .u64 t; cvta.to.shared.u64 t, %1; cvt.u32.u64 %0, t; }" : "=r"(a) : "l"(p));
    return a;
}
__device__ __forceinline__ float tanha(float x) {
    float r; asm("tanh.approx.f32 %0, %1;" : "=f"(r) : "f"(x)); return r;
}
__device__ __forceinline__ float sigm(float x) { return fmaf(0.5f, tanha(0.5f * x), 0.5f); }

__device__ __forceinline__ void ldsm_x4t(uint32_t* r, uint32_t addr) {
    asm volatile("ldmatrix.sync.aligned.m8n8.x4.trans.shared.b16 {%0,%1,%2,%3}, [%4];"
        : "=r"(r[0]), "=r"(r[1]), "=r"(r[2]), "=r"(r[3]) : "r"(addr));
}
__device__ __forceinline__ void ldsm_x2t(uint32_t* r, uint32_t addr) {
    asm volatile("ldmatrix.sync.aligned.m8n8.x2.trans.shared.b16 {%0,%1}, [%2];"
        : "=r"(r[0]), "=r"(r[1]) : "r"(addr));
}
__device__ __forceinline__ void mma16816(float* d, uint32_t a0, uint32_t a1, uint32_t a2,
                                         uint32_t a3, const uint32_t* b) {
    asm volatile("mma.sync.aligned.m16n8k16.row.col.f32.f16.f16.f32 "
        "{%0,%1,%2,%3}, {%4,%5,%6,%7}, {%8,%9}, {%0,%1,%2,%3};"
        : "+f"(d[0]), "+f"(d[1]), "+f"(d[2]), "+f"(d[3])
        : "r"(a0), "r"(a1), "r"(a2), "r"(a3), "r"(b[0]), "r"(b[1]));
}

// k permutation (32-wide blocks): virtual k (mma order) <-> actual k (h layout).
// lane qc reads actual [base+8qc, base+8qc+8) with one LDG.128; element j maps to
// virtual k = base + kfl*16 + pair*8 + 2qc + elem where j = kfl*4 + pair*2 + elem.
__device__ __forceinline__ int vk_to_ak(int vk) {
    int kfl = (vk >> 4) & 1, pair = (vk >> 3) & 1, qc = (vk >> 1) & 3, elem = vk & 1;
    return (vk & ~31) + 8 * qc + kfl * 4 + pair * 2 + elem;
}
__device__ __forceinline__ int ak_to_vk(int ak) {
    int qc = (ak >> 3) & 3, j = ak & 7;
    return (ak & ~31) + (j >> 2) * 16 + ((j >> 1) & 1) * 8 + qc * 2 + (j & 1);
}

__global__ void __launch_bounds__(NTHR, 1) lstm_mma_kernel(
    const float* __restrict__ z,     const float* __restrict__ Wz,
    const float* __restrict__ bz,    const float* __restrict__ token,
    const float* __restrict__ Wi,    const float* __restrict__ Wh,
    const float* __restrict__ bh,    const float* __restrict__ Wout,
    const float* __restrict__ bout,  float* __restrict__ out)
{
    extern __shared__ char smem[];
    const uint32_t sb = smem_u32(smem);

    const int tid  = threadIdx.x;
    const int lane = tid & 31;
    const int w    = tid >> 5;            // warp 0..7 (m-tile)
    const int mh   = blockIdx.x & 1;      // batch half (independent sync domain)
    const int jg   = blockIdx.x >> 1;     // unit group 0..63 (8 units)
    const int m0   = mh * 128;
    const int j0   = jg * 8;

    const int qr   = lane >> 2;
    const int qc   = lane & 3;
    const int row0 = w * 16 + qr;
    const int u0   = qc * 2;

    const uint32_t bgLane = sb + BG_OFF + (uint32_t)(lane & 15) * BG_PITCH
                          + (uint32_t)(lane >> 4) * 16u;
    const uint32_t boLane = sb + BO_OFF + (uint32_t)(lane & 15) * BO_PITCH;

    float* sxg = (float*)(smem + XG_OFF);
    volatile unsigned* myCnt = &g_cnt[mh * 32];

    // ---------------- one-time init ----------------
    for (int i = tid; i < 1024; i += NTHR) ((uint4*)(smem + BO_OFF))[i] = make_uint4(0, 0, 0, 0);

    // Wh slice -> fp16 smem, rows in VIRTUAL k order
    for (int idx = tid; idx < 512 * 32; idx += NTHR) {
        int vk = idx >> 5, n = idx & 31;
        int ak = vk_to_ak(vk);
        float v = __ldg(&Wh[(size_t)ak * G4H + (n >> 3) * HH + j0 + (n & 7)]);
        *(__half*)(smem + BG_OFF + (uint32_t)vk * BG_PITCH + (uint32_t)n * 2u) = __float2half_rn(v);
    }
    if (tid < 32) {
        int col = (tid >> 3) * HH + j0 + (tid & 7);
        float s = bh[col];
        #pragma unroll 4
        for (int k = 0; k < KTOK; ++k)
            s = fmaf(token[k], __ldg(&Wi[(size_t)k * G4H + col]), s);
        sxg[tid] = s;
    }
    {   // h0 = relu(z @ Wz + bz): thread -> row tid>>1, 4 units
        const int r  = tid >> 1;
        const int ub = (tid & 1) * 4;
        float a[4];
        #pragma unroll
        for (int q = 0; q < 4; ++q) a[q] = bz[j0 + ub + q];
        const float* zr = z + (size_t)(m0 + r) * KTOK;
        #pragma unroll 4
        for (int k = 0; k < KTOK; ++k) {
            float zv = __ldg(zr + k);
            float4 w4 = __ldg((const float4*)&Wz[(size_t)k * HH + j0 + ub]);
            a[0] = fmaf(zv, w4.x, a[0]); a[1] = fmaf(zv, w4.y, a[1]);
            a[2] = fmaf(zv, w4.z, a[2]); a[3] = fmaf(zv, w4.w, a[3]);
        }
        __half2* hp = (__half2*)&g_h[0][(size_t)(m0 + r) * HH + j0 + ub];
        hp[0] = __floats2half2_rn(fmaxf(a[0], 0.f), fmaxf(a[1], 0.f));
        hp[1] = __floats2half2_rn(fmaxf(a[2], 0.f), fmaxf(a[3], 0.f));
    }

    // initial counter barrier (ep = 1)
    unsigned ep = 1;
    __syncthreads();
    if (tid == 0) {
        __threadfence();
        asm volatile("red.global.add.u32 [%0], %1;" :: "l"((unsigned*)myCnt), "r"(1u) : "memory");
        while (*myCnt < ep * 64u) {}
        __threadfence();
    }
    __syncthreads();
    ++ep;

    float c4[4] = {0.f, 0.f, 0.f, 0.f};
    float2 wo0, wo1;

    // ---------------- sequential loop ----------------
    #pragma unroll 1
    for (int t = 0; t <= TT; ++t) {
        const __half* hsrc = g_h[t & 1];
        const int te = t - 1;

        const __half* aRow0 = hsrc + (size_t)(m0 + row0) * HH + 8 * qc;
        const __half* aRow8 = aRow0 + 8 * HH;
        const uint32_t boSel = boLane + (uint32_t)(t & 1) * BO_BUF;

        // A-fragment pipeline: 16 blocks of 32 k; 4-deep LDG.128 pipeline
        uint4 ra[4], rb[4];
        #pragma unroll
        for (int p = 0; p < 4; ++p) {
            ra[p] = __ldcg((const uint4*)(aRow0 + p * 32));
            rb[p] = __ldcg((const uint4*)(aRow8 + p * 32));
        }

        // prefetch Wout_t for next iteration (overlaps mainloop)
        if (t < TT) {
            const float* Wo = Wout + (size_t)t * HH * DD + jg * 2;
            wo0 = __ldcg((const float2*)(Wo + (size_t)(tid * 2) * DD));
            wo1 = __ldcg((const float2*)(Wo + (size_t)(tid * 2 + 1) * DD));
        }

        float acc[5][4];
        #pragma unroll
        for (int n = 0; n < 5; ++n)
            #pragma unroll
            for (int e = 0; e < 4; ++e) acc[n][e] = 0.f;

        #pragma unroll
        for (int b = 0; b < 16; ++b) {
            const int slot = b & 3;
            const uint4 va = ra[slot], vb = rb[slot];
            if (b + 4 < 16) {
                ra[slot] = __ldcg((const uint4*)(aRow0 + (b + 4) * 32));
                rb[slot] = __ldcg((const uint4*)(aRow8 + (b + 4) * 32));
            }
            #pragma unroll
            for (int kfl = 0; kfl < 2; ++kfl) {
                const uint32_t krow = (uint32_t)(b * 32 + kfl * 16);
                uint32_t b1[4], b2[4], b3[2];
                ldsm_x4t(b1, bgLane + krow * BG_PITCH);
                ldsm_x4t(b2, bgLane + krow * BG_PITCH + 32u);
                ldsm_x2t(b3, boSel + krow * BO_PITCH);
                const uint32_t a0 = kfl ? va.z : va.x;
                const uint32_t a1 = kfl ? vb.z : vb.x;
                const uint32_t a2 = kfl ? va.w : va.y;
                const uint32_t a3 = kfl ? vb.w : vb.y;
                mma16816(acc[0], a0, a1, a2, a3, b1);
                mma16816(acc[1], a0, a1, a2, a3, b1 + 2);
                mma16816(acc[2], a0, a1, a2, a3, b2);
                mma16816(acc[3], a0, a1, a2, a3, b2 + 2);
                mma16816(acc[4], a0, a1, a2, a3, b3);
            }
        }

        // ---- critical path: cell update + h store ----
        if (t < TT) {
            __half* hdst = &g_h[(t + 1) & 1][0];
            float hv[4];
            #pragma unroll
            for (int e = 0; e < 4; ++e) {
                const int u = u0 + (e & 1);
                float gi = sigm (acc[0][e] + sxg[u]);
                float gf = sigm (acc[1][e] + sxg[8 + u]);
                float gg = tanha(acc[2][e] + sxg[16 + u]);
                float go = sigm (acc[3][e] + sxg[24 + u]);
                float cv = gf * c4[e] + gi * gg;
                c4[e] = cv;
                hv[e] = go * tanha(cv);
            }
            __half2 h01 = __floats2half2_rn(hv[0], hv[1]);
            __half2 h23 = __floats2half2_rn(hv[2], hv[3]);
            __stcg((__half2*)&hdst[(size_t)(m0 + row0) * HH + j0 + u0], h01);
            __stcg((__half2*)&hdst[(size_t)(m0 + row0 + 8) * HH + j0 + u0], h23);
        }

        // ---- barrier arrive ----
        __syncthreads();
        if (t < TT && tid == 0) {
            __threadfence();
            asm volatile("red.global.add.u32 [%0], %1;" :: "l"((unsigned*)myCnt), "r"(1u) : "memory");
        }

        // ---- shadow work: out store + next-step BO staging (alternate buffer) ----
        if (t >= 1 && qc == 0) {
            const float2 bo = *(const float2*)&bout[te * DD + jg * 2];
            float2 o0 = make_float2(acc[4][0] + bo.x, acc[4][1] + bo.y);
            float2 o1 = make_float2(acc[4][2] + bo.x, acc[4][3] + bo.y);
            *(float2*)&out[(size_t)(m0 + row0) * TT * DD + (size_t)te * DD + jg * 2] = o0;
            *(float2*)&out[(size_t)(m0 + row0 + 8) * TT * DD + (size_t)te * DD + jg * 2] = o1;
        }
        if (t < TT) {
            const uint32_t boNext = BO_OFF + (uint32_t)((t + 1) & 1) * BO_BUF;
            __half2 p0 = __floats2half2_rn(wo0.x, wo0.y);
            __half2 p1 = __floats2half2_rn(wo1.x, wo1.y);
            *(uint32_t*)(smem + boNext + (uint32_t)ak_to_vk(tid * 2) * BO_PITCH)     = *(uint32_t*)&p0;
            *(uint32_t*)(smem + boNext + (uint32_t)ak_to_vk(tid * 2 + 1) * BO_PITCH) = *(uint32_t*)&p1;
        }

        // ---- barrier wait ----
        if (t < TT) {
            if (tid == 0) {
                while (*myCnt < ep * 64u) {}
                __threadfence();
            }
            __syncthreads();
            ++ep;
        }
    }
}

extern "C" void kernel_launch(void* const* d_in, const int* in_sizes, int n_in,
                              void* d_out, int out_size) {
    const float* z     = (const float*)d_in[0];
    const float* Wz    = (const float*)d_in[1];
    const float* bz    = (const float*)d_in[2];
    const float* token = (const float*)d_in[3];
    const float* Wi    = (const float*)d_in[4];
    const float* Wh    = (const float*)d_in[5];
    const float* bh    = (const float*)d_in[6];
    const float* Wout  = (const float*)d_in[7];
    const float* bout  = (const float*)d_in[8];
    float* out = (float*)d_out;

    cudaFuncSetAttribute(lstm_mma_kernel, cudaFuncAttributeMaxDynamicSharedMemorySize, SMEM_BYTES);
    reset_kernel<<<1, 64>>>();
    lstm_mma_kernel<<<NCTA, NTHR, SMEM_BYTES>>>(z, Wz, bz, token, Wi, Wh, bh, Wout, bout, out);
}